// round 1
// baseline (speedup 1.0000x reference)
#include <cuda_runtime.h>

#define N_NODES   1000000
#define DIM       128
#define B_GRAPHS  2048
#define CHUNK     128
#define G_PER_BLK 16

// Scratch (no cudaMalloc allowed): pool accumulator + transposed W
__device__ float g_pool[B_GRAPHS * DIM];
__device__ float g_Wt[DIM * DIM];

// ---------------------------------------------------------------------------
// Kernel 0a: zero the pool accumulator (graph replays re-run atomics)
// ---------------------------------------------------------------------------
__global__ void zero_pool_kernel() {
    int i = blockIdx.x * blockDim.x + threadIdx.x;
    if (i < B_GRAPHS * DIM) g_pool[i] = 0.0f;
}

// ---------------------------------------------------------------------------
// Kernel 0b: transpose W (64KB) so the GEMM reads it coalesced.
// g_Wt[k*DIM + j] = W[j*DIM + k]
// ---------------------------------------------------------------------------
__global__ void transpose_W_kernel(const float* __restrict__ W) {
    int i = blockIdx.x * blockDim.x + threadIdx.x;
    if (i < DIM * DIM) {
        int j = i >> 7;
        int k = i & (DIM - 1);
        g_Wt[k * DIM + j] = W[i];
    }
}

// ---------------------------------------------------------------------------
// Kernel 1: segment sum. segment_ids is SORTED, so each block processes
// CHUNK contiguous rows, accumulating in registers and flushing with an
// atomicAdd only at segment boundaries / chunk edges (~1.3M atomics total).
// blockDim = DIM (thread t owns dim column t); loads are fully coalesced.
// ---------------------------------------------------------------------------
__global__ void seg_sum_kernel(const float* __restrict__ h,
                               const int*   __restrict__ seg) {
    int row0 = blockIdx.x * CHUNK;
    int row1 = row0 + CHUNK;
    if (row1 > N_NODES) row1 = N_NODES;
    int t = threadIdx.x;

    int sFirst = __ldg(&seg[row0]);
    int sLast  = __ldg(&seg[row1 - 1]);

    if (sFirst == sLast) {
        // Fast path (~74% of chunks): single segment, pure streaming sum.
        float acc = 0.0f;
        #pragma unroll 8
        for (int r = row0; r < row1; ++r)
            acc += __ldg(&h[r * DIM + t]);
        atomicAdd(&g_pool[sFirst * DIM + t], acc);
    } else {
        // Boundary path: per-row segment check (sorted -> few flushes).
        float acc = 0.0f;
        int cur = sFirst;
        for (int r = row0; r < row1; ++r) {
            int   s = __ldg(&seg[r]);
            float v = __ldg(&h[r * DIM + t]);
            if (s != cur) {
                atomicAdd(&g_pool[cur * DIM + t], acc);
                acc = 0.0f;
                cur = s;
            }
            acc += v;
        }
        atomicAdd(&g_pool[cur * DIM + t], acc);
    }
}

// ---------------------------------------------------------------------------
// Kernel 2: vn_out = vn_h + relu((vn_h + pool) @ W^T + b)
// blockDim = DIM (thread j computes output column j for G_PER_BLK graphs).
// x tiles live in smem (warp-broadcast reads); W^T read coalesced from L2.
// ---------------------------------------------------------------------------
__global__ void vn_update_kernel(const float* __restrict__ vn_h,
                                 const float* __restrict__ b,
                                 float*       __restrict__ vn_out) {
    __shared__ float sx[G_PER_BLK][DIM];
    int j  = threadIdx.x;
    int g0 = blockIdx.x * G_PER_BLK;

    #pragma unroll
    for (int gl = 0; gl < G_PER_BLK; ++gl) {
        int idx = (g0 + gl) * DIM + j;
        sx[gl][j] = vn_h[idx] + g_pool[idx];
    }
    __syncthreads();

    float acc[G_PER_BLK];
    #pragma unroll
    for (int gl = 0; gl < G_PER_BLK; ++gl) acc[gl] = 0.0f;

    #pragma unroll 4
    for (int k = 0; k < DIM; ++k) {
        float w = g_Wt[k * DIM + j];   // coalesced: consecutive j
        #pragma unroll
        for (int gl = 0; gl < G_PER_BLK; ++gl)
            acc[gl] = fmaf(sx[gl][k], w, acc[gl]);  // sx: smem broadcast
    }

    float bj = __ldg(&b[j]);
    #pragma unroll
    for (int gl = 0; gl < G_PER_BLK; ++gl) {
        int idx = (g0 + gl) * DIM + j;
        float v = fmaxf(acc[gl] + bj, 0.0f);
        vn_out[idx] = vn_h[idx] + v;
    }
}

// ---------------------------------------------------------------------------
// Kernel 3: h_out = h + vn_out[segment_ids]. float4 streaming.
// 32 consecutive lanes cover one row -> seg load is warp-uniform,
// vn gather is one coalesced 512B L2-resident row per warp.
// ---------------------------------------------------------------------------
__global__ void broadcast_add_kernel(const float4* __restrict__ h4,
                                     const float4* __restrict__ vn4,
                                     const int*    __restrict__ seg,
                                     float4*       __restrict__ out4) {
    unsigned idx = blockIdx.x * blockDim.x + threadIdx.x;   // < 32M
    if (idx >= (unsigned)N_NODES * (DIM / 4)) return;
    unsigned row = idx >> 5;          // DIM/4 = 32 float4 per row
    unsigned c   = idx & 31u;
    int s = __ldg(&seg[row]);
    float4 hv = __ldg(&h4[idx]);
    float4 vv = __ldg(&vn4[(unsigned)s * 32u + c]);
    out4[idx] = make_float4(hv.x + vv.x, hv.y + vv.y,
                            hv.z + vv.z, hv.w + vv.w);
}

// ---------------------------------------------------------------------------
// Launch: out = [vn_out (B*DIM floats) | h_out (N*DIM floats)]
// ---------------------------------------------------------------------------
extern "C" void kernel_launch(void* const* d_in, const int* in_sizes, int n_in,
                              void* d_out, int out_size) {
    const float* h    = (const float*)d_in[0];
    const float* vn_h = (const float*)d_in[1];
    const float* W    = (const float*)d_in[2];
    const float* b    = (const float*)d_in[3];
    const int*   seg  = (const int*)  d_in[4];

    float* out    = (float*)d_out;
    float* vn_out = out;                       // [B, DIM]
    float* h_out  = out + B_GRAPHS * DIM;      // [N, DIM] (1MB offset, 16B-aligned)

    zero_pool_kernel<<<(B_GRAPHS * DIM + 255) / 256, 256>>>();
    transpose_W_kernel<<<(DIM * DIM + 255) / 256, 256>>>(W);
    seg_sum_kernel<<<(N_NODES + CHUNK - 1) / CHUNK, DIM>>>(h, seg);
    vn_update_kernel<<<B_GRAPHS / G_PER_BLK, DIM>>>(vn_h, b, vn_out);

    unsigned total4 = (unsigned)N_NODES * (DIM / 4);
    broadcast_add_kernel<<<(total4 + 255) / 256, 256>>>(
        (const float4*)h, (const float4*)vn_out, seg, (float4*)h_out);
}